// round 13
// baseline (speedup 1.0000x reference)
#include <cuda_runtime.h>
#include <cuda_fp16.h>
#include <cstdint>
#include <cstddef>

// ============================================================
// out = L1rownorm(A[8192,8192]) @ X[8192,512] @ W[512,256] + bias
//   Xh = fp16(X)                                 (prep kernel, L2-fast)
//   Yt[256,8192](fp16) = W^T @ Xh^T              (fp16 HMMA; W loaded fp32,
//        converted in-register, stored [k][m] in smem, ldmatrix.trans)
//   out[m,:] = (A[m,:] @ Y)/sum(A[m,:]) + bias   (R10 gemm2, tile 128x64)
// ============================================================

#define N_ROWS 8192
#define F_IN   512
#define F_OUT  256

#define PAH 40                       // halves per smem row (80 B)
#define CK 32

// ---- GEMM1: tile 64(W cols) x 128(X rows) ----
#define WP 72                        // W smem pitch in halves (144 B)
#define WC_ST (32 * WP * 2)          // 4608 B per W conv stage (2 stages)
#define XB_OFF (2 * WC_ST)           // 9216
#define XB_ST (128 * PAH * 2)        // 10240 B per X async stage (6 stages)
#define G1_SMEM (XB_OFF + 6 * XB_ST) // 70656 -> 2 CTAs/SM

// ---- GEMM2 (R10 config): tile 128x64 ----
#define T2_M 128
#define T2_N 64
#define A_ST  (T2_M * PAH * 2)       // 10240
#define B_ST  (T2_N * PAH * 2)       // 5120
#define B_OFF (4 * A_ST)             // 4 A stages
#define RS_OFF (B_OFF + 8 * B_ST)    // 8 B stages -> 81920
#define T2_SMEM (RS_OFF + 128 * 4)   // 82432 -> 2 CTAs/SM

__device__ __align__(1024) __half g_Xh[(size_t)N_ROWS * F_IN];
__device__ __align__(1024) __half g_Yt[(size_t)F_OUT * N_ROWS];

// ---------------- device helpers ----------------
__device__ __forceinline__ uint32_t pack_h2(float lo, float hi) {
    uint32_t u;
    asm("cvt.rn.f16x2.f32 %0, %1, %2;" : "=r"(u) : "f"(hi), "f"(lo));
    return u;
}
__device__ __forceinline__ void mma_f16_k16(float* c, const uint32_t* a, const uint32_t* b) {
    asm volatile(
        "mma.sync.aligned.m16n8k16.row.col.f32.f16.f16.f32 "
        "{%0,%1,%2,%3}, {%4,%5,%6,%7}, {%8,%9}, {%0,%1,%2,%3};"
        : "+f"(c[0]), "+f"(c[1]), "+f"(c[2]), "+f"(c[3])
        : "r"(a[0]), "r"(a[1]), "r"(a[2]), "r"(a[3]), "r"(b[0]), "r"(b[1]));
}
__device__ __forceinline__ void cpa16(uint32_t s, const void* g) {
    asm volatile("cp.async.cg.shared.global [%0], [%1], 16;" :: "r"(s), "l"(g));
}
__device__ __forceinline__ void ldsm4(uint32_t& r0, uint32_t& r1, uint32_t& r2, uint32_t& r3,
                                      uint32_t addr) {
    asm volatile("ldmatrix.sync.aligned.m8n8.x4.shared.b16 {%0,%1,%2,%3}, [%4];"
                 : "=r"(r0), "=r"(r1), "=r"(r2), "=r"(r3) : "r"(addr));
}
__device__ __forceinline__ void ldsm4t(uint32_t& r0, uint32_t& r1, uint32_t& r2, uint32_t& r3,
                                       uint32_t addr) {
    asm volatile("ldmatrix.sync.aligned.m8n8.x4.trans.shared.b16 {%0,%1,%2,%3}, [%4];"
                 : "=r"(r0), "=r"(r1), "=r"(r2), "=r"(r3) : "r"(addr));
}
__device__ __forceinline__ uint32_t smem_u32(const void* p) {
    uint32_t a;
    asm("{ .reg .u64 t; cvta.to.shared.u64 t, %1; cvt.u32.u64 %0, t; }" : "=r"(a) : "l"(p));
    return a;
}

// ---------------- prep: Xh = fp16(X) ----------------
__global__ void __launch_bounds__(256, 1) prep_xh(const float* __restrict__ x,
                                                  __half* __restrict__ xh) {
    int i = blockIdx.x * 256 + threadIdx.x;
    float4 v = reinterpret_cast<const float4*>(x)[i];
    uint2 o;
    o.x = pack_h2(v.x, v.y);
    o.y = pack_h2(v.z, v.w);
    reinterpret_cast<uint2*>(xh)[i] = o;
}

// ---------------- GEMM1: Yt[256,8192] = W^T @ Xh^T (W transposed via ldsm.trans) ----
__global__ void __launch_bounds__(256, 2) gemm1_f16(
    const float* __restrict__ Wf,     // W  [512,256] fp32
    const __half* __restrict__ Q,     // Xh [8192,512] fp16
    __half* __restrict__ out)         // Yt [256,8192] fp16
{
    extern __shared__ char smem[];
    const uint32_t sbase = smem_u32(smem);

    const int tid  = threadIdx.x;
    const int lane = tid & 31;
    const int wid  = tid >> 5;
    const int gid  = lane >> 2;
    const int tig  = lane & 3;
    const int wm   = wid >> 2;            // 0..1 (M strips of 32; W^T rows)
    const int wn   = wid & 3;             // 0..3 (N strips of 32; X rows)
    const int lrow = lane & 15;
    const int lhi  = (lane >> 4) & 1;
    // ldmatrix.trans lane addressing for the [k][m] W tile
    const int ktr = ((lane >> 4) << 3) + (lane & 7);    // k-row within 16-group
    const int mof = ((lane >> 3) & 1) << 3;             // m col offset 0/8

    const int mtile = blockIdx.x >> 6;    // 0..3
    const int ntile = blockIdx.x & 63;    // 0..63
    const int m0 = mtile * 64;            // W column block
    const int n0 = ntile * 128;
    const int kchunks = F_IN / CK;        // 16

    // W producer: 32 fi-rows x 64 fo-cols fp32 per chunk
    const int rf = tid >> 3;              // 0..31 (fi row within chunk)
    const int sf = tid & 7;               // 0..7  (8-float segment)
    const float* gW = Wf + (size_t)rf * F_OUT + m0 + sf * 8;

    // X async producer: 128 rows, 64B/row per chunk (2 loads/thread)
    const int rw = tid >> 2;              // 0..63
    const int sg = tid & 3;               // 0..3
    const __half* gX = Q + (size_t)(n0 + rw) * F_IN + sg * 8;

    float acc[2][4][4];
    #pragma unroll
    for (int mi = 0; mi < 2; mi++)
        #pragma unroll
        for (int ni = 0; ni < 4; ni++)
            #pragma unroll
            for (int i = 0; i < 4; i++) acc[mi][ni][i] = 0.f;

    auto issueX = [&](int kc, int s6) {
        if (kc < kchunks) {
            uint32_t sX = sbase + XB_OFF + s6 * XB_ST + rw * (PAH * 2) + sg * 16;
            cpa16(sX,                  gX + (size_t)kc * CK);
            cpa16(sX + 64 * (PAH * 2), gX + (size_t)64 * F_IN + (size_t)kc * CK);
        }
        asm volatile("cp.async.commit_group;" ::: "memory");
    };
    auto ldW = [&](int kc, float4& w0, float4& w1) {
        const float* p = gW + (size_t)kc * CK * F_OUT;
        w0 = *(const float4*)(p);
        w1 = *(const float4*)(p + 4);
    };

    float4 w0, w1;
    ldW(0, w0, w1);
    issueX(0, 0);
    issueX(1, 1);
    issueX(2, 2);
    issueX(3, 3);

    int s6c = 0, s6p = 4, p2 = 0;
    for (int kc = 0; kc < kchunks; kc++) {
        asm volatile("cp.async.wait_group %0;" :: "n"(3) : "memory");

        // convert + store W chunk [k][m] fp16, prefetch next
        {
            const uint32_t ww = sbase + p2 * WC_ST + (rf * WP + sf * 8) * 2;
            uint32_t h0 = pack_h2(w0.x, w0.y);
            uint32_t h1 = pack_h2(w0.z, w0.w);
            uint32_t h2 = pack_h2(w1.x, w1.y);
            uint32_t h3 = pack_h2(w1.z, w1.w);
            asm volatile("st.shared.v4.b32 [%0], {%1,%2,%3,%4};"
                         :: "r"(ww), "r"(h0), "r"(h1), "r"(h2), "r"(h3));
        }
        const int kn = (kc + 1 < kchunks) ? kc + 1 : kc;
        ldW(kn, w0, w1);

        __syncthreads();

        issueX(kc + 4, s6p);

        const uint32_t wBase = sbase + p2 * WC_ST;
        const uint32_t bBase = sbase + XB_OFF + s6c * XB_ST;
        #pragma unroll
        for (int kh = 0; kh < 2; kh++) {
            uint32_t af[2][4], bf[4][2];
            #pragma unroll
            for (int mi = 0; mi < 2; mi++) {
                const int ms = wm * 32 + mi * 16;
                uint32_t ad = wBase + (((kh * 16 + ktr) * WP) + ms + mof) * 2;
                ldsm4t(af[mi][0], af[mi][1], af[mi][2], af[mi][3], ad);
            }
            #pragma unroll
            for (int np = 0; np < 2; np++) {
                uint32_t bd = bBase + ((wn * 32 + np * 16 + lrow) * PAH + kh * 16 + lhi * 8) * 2;
                uint32_t r0, r1, r2, r3;
                ldsm4(r0, r1, r2, r3, bd);
                bf[np * 2 + 0][0] = r0; bf[np * 2 + 0][1] = r2;
                bf[np * 2 + 1][0] = r1; bf[np * 2 + 1][1] = r3;
            }
            #pragma unroll
            for (int mi = 0; mi < 2; mi++)
                #pragma unroll
                for (int ni = 0; ni < 4; ni++)
                    mma_f16_k16(acc[mi][ni], af[mi], bf[ni]);
        }

        s6c = (s6c == 5) ? 0 : s6c + 1;
        s6p = (s6p == 5) ? 0 : s6p + 1;
        p2 ^= 1;
    }

    // epilogue: Yt fp16
    #pragma unroll
    for (int mi = 0; mi < 2; mi++) {
        const int r0 = m0 + wm * 32 + mi * 16 + gid;
        #pragma unroll
        for (int ni = 0; ni < 4; ni++) {
            const int cg = n0 + wn * 32 + ni * 8 + tig * 2;
            *(uint32_t*)(out + (size_t)r0 * N_ROWS + cg) =
                pack_h2(acc[mi][ni][0], acc[mi][ni][1]);
            *(uint32_t*)(out + (size_t)(r0 + 8) * N_ROWS + cg) =
                pack_h2(acc[mi][ni][2], acc[mi][ni][3]);
        }
    }
}

// ---------------- GEMM2 (R10 config): out = (A @ Yt^T)*inv_rowsum + bias ----------------
__global__ void __launch_bounds__(256, 2) gemm2_f16(
    const float* __restrict__ A, const __half* __restrict__ Yt,
    float* __restrict__ out, const float* __restrict__ bias)
{
    extern __shared__ char smem[];
    const uint32_t sbase = smem_u32(smem);

    const int tid  = threadIdx.x;
    const int lane = tid & 31;
    const int wid  = tid >> 5;
    const int gid  = lane >> 2;
    const int tig  = lane & 3;
    const int wm   = wid >> 1;            // 0..3 (M strips of 32)
    const int wn   = wid & 1;             // 0..1 (N strips of 32)
    const int lrow = lane & 15;
    const int lhi  = (lane >> 4) & 1;

    const int mtile = blockIdx.x >> 2;    // 64
    const int ntile = blockIdx.x & 3;     // 4
    const int m0 = mtile * T2_M;
    const int n0 = ntile * T2_N;
    const int kchunks = N_ROWS / CK;      // 256

    const int ra = tid >> 3;
    const int sa = tid & 7;
    const int rb = tid >> 2;
    const int sb = tid & 3;
    const float*  gA = A  + (size_t)(m0 + ra) * N_ROWS + sa * 4;
    const __half* gB = Yt + (size_t)(n0 + rb) * N_ROWS + sb * 8;

    float acc[2][4][4];
    #pragma unroll
    for (int mi = 0; mi < 2; mi++)
        #pragma unroll
        for (int ni = 0; ni < 4; ni++)
            #pragma unroll
            for (int i = 0; i < 4; i++) acc[mi][ni][i] = 0.f;
    float rsum[4] = {0.f, 0.f, 0.f, 0.f};

    auto issueB = [&](int kc) {
        if (kc < kchunks) {
            cpa16(sbase + B_OFF + (kc & 7) * B_ST + rb * (PAH * 2) + sb * 16,
                  gB + (size_t)kc * CK);
            cpa16(sbase + B_OFF + ((kc + 1) & 7) * B_ST + rb * (PAH * 2) + sb * 16,
                  gB + (size_t)(kc + 1) * CK);
        }
        asm volatile("cp.async.commit_group;" ::: "memory");
    };
    auto ldA = [&](int kc, float4* v) {
        #pragma unroll
        for (int i = 0; i < 4; i++)
            v[i] = *(const float4*)(gA + (size_t)i * 32 * N_ROWS + (size_t)kc * CK);
    };
    auto stA = [&](int kc, const float4* v) {
        const uint32_t aw = sbase + (kc & 3) * A_ST + ra * (PAH * 2) + sa * 8;
        #pragma unroll
        for (int i = 0; i < 4; i++) {
            uint32_t h01 = pack_h2(v[i].x, v[i].y);
            uint32_t h23 = pack_h2(v[i].z, v[i].w);
            asm volatile("st.shared.v2.b32 [%0], {%1,%2};"
                         :: "r"(aw + i * 32 * (PAH * 2)), "r"(h01), "r"(h23));
            rsum[i] += (v[i].x + v[i].y) + (v[i].z + v[i].w);
        }
    };
    auto mmaChunk = [&](int kc) {
        const uint32_t aBase = sbase + (kc & 3) * A_ST;
        const uint32_t bBase = sbase + B_OFF + (kc & 7) * B_ST;
        #pragma unroll
        for (int ks = 0; ks < 2; ks++) {
            uint32_t af[2][4], bf[4][2];
            #pragma unroll
            for (int mi = 0; mi < 2; mi++) {
                uint32_t ad = aBase + ((wm * 32 + mi * 16 + lrow) * PAH + ks * 16 + lhi * 8) * 2;
                ldsm4(af[mi][0], af[mi][1], af[mi][2], af[mi][3], ad);
            }
            #pragma unroll
            for (int np = 0; np < 2; np++) {
                uint32_t bd = bBase + ((wn * 32 + np * 16 + lrow) * PAH + ks * 16 + lhi * 8) * 2;
                uint32_t r0, r1, r2, r3;
                ldsm4(r0, r1, r2, r3, bd);
                bf[np * 2 + 0][0] = r0; bf[np * 2 + 0][1] = r2;
                bf[np * 2 + 1][0] = r1; bf[np * 2 + 1][1] = r3;
            }
            #pragma unroll
            for (int mi = 0; mi < 2; mi++)
                #pragma unroll
                for (int ni = 0; ni < 4; ni++)
                    mma_f16_k16(acc[mi][ni], af[mi], bf[ni]);
        }
    };

    // prologue
    float4 vA0[4], vA1[4];
    ldA(0, vA0);
    ldA(1, vA1);
    issueB(0);
    issueB(2);

    for (int kc = 0; kc < kchunks; kc += 2) {
        asm volatile("cp.async.wait_group %0;" :: "n"(1) : "memory");

        stA(kc, vA0);
        stA(kc + 1, vA1);
        int kn0 = kc + 2, kn1 = kc + 3;
        if (kn1 >= kchunks) { kn0 = kchunks - 2; kn1 = kchunks - 1; }
        ldA(kn0, vA0);
        ldA(kn1, vA1);

        __syncthreads();

        issueB(kc + 4);

        mmaChunk(kc);
        mmaChunk(kc + 1);
    }

    // rowsum reduce (8 lanes per row group)
    #pragma unroll
    for (int i = 0; i < 4; i++) {
        rsum[i] += __shfl_down_sync(0xffffffffu, rsum[i], 4, 8);
        rsum[i] += __shfl_down_sync(0xffffffffu, rsum[i], 2, 8);
        rsum[i] += __shfl_down_sync(0xffffffffu, rsum[i], 1, 8);
    }
    float* rs = (float*)(smem + RS_OFF);
    if (sa == 0) {
        #pragma unroll
        for (int i = 0; i < 4; i++)
            rs[i * 32 + ra] = 1.f / fmaxf(rsum[i], 1e-12f);
    }
    __syncthreads();

    // epilogue
    #pragma unroll
    for (int mi = 0; mi < 2; mi++) {
        const int r0 = wm * 32 + mi * 16 + gid;
        const float i0 = rs[r0];
        const float i1 = rs[r0 + 8];
        #pragma unroll
        for (int ni = 0; ni < 4; ni++) {
            const int cg = n0 + wn * 32 + ni * 8 + tig * 2;
            float2 bv = *(const float2*)(bias + cg);
            float2 v0, v1;
            v0.x = acc[mi][ni][0] * i0 + bv.x;
            v0.y = acc[mi][ni][1] * i0 + bv.y;
            v1.x = acc[mi][ni][2] * i1 + bv.x;
            v1.y = acc[mi][ni][3] * i1 + bv.y;
            *(float2*)(out + (size_t)(m0 + r0) * F_OUT + cg) = v0;
            *(float2*)(out + (size_t)(m0 + r0 + 8) * F_OUT + cg) = v1;
        }
    }
}

// ---------------- host ----------------
extern "C" void kernel_launch(void* const* d_in, const int* in_sizes, int n_in,
                              void* d_out, int out_size) {
    const float *A = nullptr, *X = nullptr, *W = nullptr, *Bi = nullptr;
    for (int i = 0; i < n_in; i++) {
        long s = in_sizes[i];
        if (s == (long)N_ROWS * N_ROWS)      A  = (const float*)d_in[i];
        else if (s == (long)N_ROWS * F_IN)   X  = (const float*)d_in[i];
        else if (s == (long)F_IN * F_OUT)    W  = (const float*)d_in[i];
        else if (s == (long)F_OUT)           Bi = (const float*)d_in[i];
    }

    void *xh = nullptr, *yt = nullptr;
    cudaGetSymbolAddress(&xh, g_Xh);
    cudaGetSymbolAddress(&yt, g_Yt);

    cudaFuncSetAttribute(gemm1_f16, cudaFuncAttributeMaxDynamicSharedMemorySize, G1_SMEM);
    cudaFuncSetAttribute(gemm2_f16, cudaFuncAttributeMaxDynamicSharedMemorySize, T2_SMEM);

    prep_xh<<<(N_ROWS * F_IN / 4) / 256, 256>>>(X, (__half*)xh);

    // GEMM1: Yt[256,8192] = W^T @ Xh^T  (W transposed in-kernel; 4x64 = 256 CTAs)
    gemm1_f16<<<4 * 64, 256, G1_SMEM>>>(W, (const __half*)xh, (__half*)yt);

    // GEMM2: out[8192,256] = (A @ Yt^T)*inv_rowsum + bias  (64 x 4 = 256 CTAs)
    gemm2_f16<<<64 * 4, 256, T2_SMEM>>>(A, (const __half*)yt, (float*)d_out, Bi);
}

// round 14
// speedup vs baseline: 1.0071x; 1.0071x over previous
#include <cuda_runtime.h>
#include <cuda_fp16.h>
#include <cstdint>
#include <cstddef>

// ============================================================
// out = L1rownorm(A[8192,8192]) @ X[8192,512] @ W[512,256] + bias
//   prep_all: Xh = fp16(X)  AND  Wth = fp16(W^T)  (one merged launch)
//   Yt[256,8192](fp16) = Wth @ Xh^T          (fp16 HMMA, tile 64x128, 256 CTAs)
//   out[m,:] = (A[m,:] @ Y)/sum(A[m,:]) + bias  (gemm2: tile 128x64, 256 CTAs)
// ============================================================

#define N_ROWS 8192
#define F_IN   512
#define F_OUT  256

// ---- GEMM1 (fp16): tile 64x128 ----
#define PAH 40                       // halves per smem row (80 B)
#define A_ST1 (64 * PAH * 2)         // 5120
#define B_ST1 (128 * PAH * 2)        // 10240
#define STAGE1 (A_ST1 + B_ST1)       // 15360
#define G1_SMEM (3 * STAGE1)         // 46080

// ---- GEMM2 (fp16): tile 128x64 ----
#define T2_M 128
#define T2_N 64
#define CK 32
#define A_ST  (T2_M * PAH * 2)       // 10240
#define B_ST  (T2_N * PAH * 2)       // 5120
#define B_OFF (4 * A_ST)             // 4 A stages
#define RS_OFF (B_OFF + 8 * B_ST)    // 8 B stages -> 81920
#define T2_SMEM (RS_OFF + 128 * 4)   // 82432 -> 2 CTAs/SM

// merged prep grid split
#define XH_BLOCKS 2048               // 2 float4 per thread: 2048*256*2 = 1048576 float4
#define XH_HALF   (XH_BLOCKS * 256)  // 524288

__device__ __align__(1024) __half g_Xh[(size_t)N_ROWS * F_IN];
__device__ __align__(1024) __half g_Wth[(size_t)F_OUT * F_IN];
__device__ __align__(1024) __half g_Yt[(size_t)F_OUT * N_ROWS];

// ---------------- device helpers ----------------
__device__ __forceinline__ uint32_t pack_h2(float lo, float hi) {
    uint32_t u;
    asm("cvt.rn.f16x2.f32 %0, %1, %2;" : "=r"(u) : "f"(hi), "f"(lo));
    return u;
}
__device__ __forceinline__ void mma_f16_k16(float* c, const uint32_t* a, const uint32_t* b) {
    asm volatile(
        "mma.sync.aligned.m16n8k16.row.col.f32.f16.f16.f32 "
        "{%0,%1,%2,%3}, {%4,%5,%6,%7}, {%8,%9}, {%0,%1,%2,%3};"
        : "+f"(c[0]), "+f"(c[1]), "+f"(c[2]), "+f"(c[3])
        : "r"(a[0]), "r"(a[1]), "r"(a[2]), "r"(a[3]), "r"(b[0]), "r"(b[1]));
}
__device__ __forceinline__ void cpa16(uint32_t s, const void* g) {
    asm volatile("cp.async.cg.shared.global [%0], [%1], 16;" :: "r"(s), "l"(g));
}
__device__ __forceinline__ void ldsm4(uint32_t& r0, uint32_t& r1, uint32_t& r2, uint32_t& r3,
                                      uint32_t addr) {
    asm volatile("ldmatrix.sync.aligned.m8n8.x4.shared.b16 {%0,%1,%2,%3}, [%4];"
                 : "=r"(r0), "=r"(r1), "=r"(r2), "=r"(r3) : "r"(addr));
}
__device__ __forceinline__ uint32_t smem_u32(const void* p) {
    uint32_t a;
    asm("{ .reg .u64 t; cvta.to.shared.u64 t, %1; cvt.u32.u64 %0, t; }" : "=r"(a) : "l"(p));
    return a;
}

// ---------------- merged prep: Xh = fp16(X), Wth = fp16(W^T) ----------------
__global__ void __launch_bounds__(256, 1) prep_all(
    const float* __restrict__ x, __half* __restrict__ xh,
    const float* __restrict__ w, __half* __restrict__ wth)
{
    __shared__ float t[32][33];
    const int b = blockIdx.x;
    if (b < XH_BLOCKS) {
        // X conversion: 2 independent float4s per thread (MLP 2)
        const int i = b * 256 + threadIdx.x;
        float4 v0 = reinterpret_cast<const float4*>(x)[i];
        float4 v1 = reinterpret_cast<const float4*>(x)[i + XH_HALF];
        uint2 o0, o1;
        o0.x = pack_h2(v0.x, v0.y); o0.y = pack_h2(v0.z, v0.w);
        o1.x = pack_h2(v1.x, v1.y); o1.y = pack_h2(v1.z, v1.w);
        reinterpret_cast<uint2*>(xh)[i] = o0;
        reinterpret_cast<uint2*>(xh)[i + XH_HALF] = o1;
    } else {
        // W transpose: 128 blocks, 32x32 smem tiles
        const int bid = b - XH_BLOCKS;
        const int tx = threadIdx.x & 31;
        const int ty = threadIdx.x >> 5;          // 0..7
        const int fo0 = (bid & 7) * 32;
        const int fi0 = (bid >> 3) * 32;
        #pragma unroll
        for (int r = 0; r < 32; r += 8)
            t[ty + r][tx] = w[(size_t)(fi0 + ty + r) * F_OUT + fo0 + tx];
        __syncthreads();
        #pragma unroll
        for (int r = 0; r < 32; r += 8)
            wth[(size_t)(fo0 + ty + r) * F_IN + fi0 + tx] = __float2half_rn(t[tx][ty + r]);
    }
}

// ---------------- GEMM1 (fp16): Yt[256,8192] = Wth @ Xh^T, tile 64x128 ----------------
__global__ void __launch_bounds__(256, 2) gemm1_f16(
    const __half* __restrict__ P, const __half* __restrict__ Q,
    __half* __restrict__ out)
{
    extern __shared__ char smem[];
    const uint32_t sbase = smem_u32(smem);

    const int tid  = threadIdx.x;
    const int lane = tid & 31;
    const int wid  = tid >> 5;
    const int gid  = lane >> 2;
    const int tig  = lane & 3;
    const int wm   = wid >> 2;            // 0..1 (M strips of 32)
    const int wn   = wid & 3;             // 0..3 (N strips of 32)
    const int lrow = lane & 15;
    const int lhi  = (lane >> 4) & 1;

    const int mtile = blockIdx.x >> 6;    // 0..3
    const int ntile = blockIdx.x & 63;    // 0..63
    const int m0 = mtile * 64;
    const int n0 = ntile * 128;
    const int kchunks = F_IN / CK;        // 16

    const int rw = tid >> 2;              // 0..63
    const int sg = tid & 3;               // 0..3
    const __half* gA = P + (size_t)(m0 + rw) * F_IN + sg * 8;
    const __half* gB = Q + (size_t)(n0 + rw) * F_IN + sg * 8;

    auto issue = [&](int kc, int s) {
        uint32_t sA = sbase + s * STAGE1 + rw * 80 + sg * 16;
        uint32_t sB = sA + A_ST1;
        cpa16(sA,           gA + kc * CK);
        cpa16(sB,           gB + kc * CK);
        cpa16(sB + 64 * 80, gB + kc * CK + (size_t)64 * F_IN);
        asm volatile("cp.async.commit_group;" ::: "memory");
    };

    float acc[2][4][4];
    #pragma unroll
    for (int mi = 0; mi < 2; mi++)
        #pragma unroll
        for (int ni = 0; ni < 4; ni++)
            #pragma unroll
            for (int i = 0; i < 4; i++) acc[mi][ni][i] = 0.f;

    issue(0, 0);
    issue(1, 1);

    int s_c = 0, s_p = 2;
    for (int kc = 0; kc < kchunks; kc++) {
        asm volatile("cp.async.wait_group %0;" :: "n"(1) : "memory");
        __syncthreads();
        const uint32_t aBase = sbase + s_c * STAGE1;
        const uint32_t bBase = aBase + A_ST1;

        #pragma unroll
        for (int kh = 0; kh < 2; kh++) {
            uint32_t af[2][4], bf[4][2];
            #pragma unroll
            for (int mi = 0; mi < 2; mi++) {
                uint32_t ad = aBase + ((wm * 32 + mi * 16 + lrow) * PAH + kh * 16 + lhi * 8) * 2;
                ldsm4(af[mi][0], af[mi][1], af[mi][2], af[mi][3], ad);
            }
            #pragma unroll
            for (int np = 0; np < 2; np++) {
                uint32_t bd = bBase + ((wn * 32 + np * 16 + lrow) * PAH + kh * 16 + lhi * 8) * 2;
                uint32_t r0, r1, r2, r3;
                ldsm4(r0, r1, r2, r3, bd);
                bf[np * 2 + 0][0] = r0; bf[np * 2 + 0][1] = r2;
                bf[np * 2 + 1][0] = r1; bf[np * 2 + 1][1] = r3;
            }
            #pragma unroll
            for (int mi = 0; mi < 2; mi++)
                #pragma unroll
                for (int ni = 0; ni < 4; ni++)
                    mma_f16_k16(acc[mi][ni], af[mi], bf[ni]);
        }

        if (kc + 2 < kchunks) issue(kc + 2, s_p);
        else asm volatile("cp.async.commit_group;" ::: "memory");
        if (++s_c == 3) s_c = 0;
        if (++s_p == 3) s_p = 0;
    }

    #pragma unroll
    for (int mi = 0; mi < 2; mi++) {
        const int r0 = m0 + wm * 32 + mi * 16 + gid;
        #pragma unroll
        for (int ni = 0; ni < 4; ni++) {
            const int cg = n0 + wn * 32 + ni * 8 + tig * 2;
            *(uint32_t*)(out + (size_t)r0 * N_ROWS + cg) =
                pack_h2(acc[mi][ni][0], acc[mi][ni][1]);
            *(uint32_t*)(out + (size_t)(r0 + 8) * N_ROWS + cg) =
                pack_h2(acc[mi][ni][2], acc[mi][ni][3]);
        }
    }
}

// ---------------- GEMM2: out = (A @ Yt^T)*inv_rowsum + bias ----------------
__global__ void __launch_bounds__(256, 2) gemm2_f16(
    const float* __restrict__ A, const __half* __restrict__ Yt,
    float* __restrict__ out, const float* __restrict__ bias)
{
    extern __shared__ char smem[];
    const uint32_t sbase = smem_u32(smem);

    const int tid  = threadIdx.x;
    const int lane = tid & 31;
    const int wid  = tid >> 5;
    const int gid  = lane >> 2;
    const int tig  = lane & 3;
    const int wm   = wid >> 1;            // 0..3 (M strips of 32)
    const int wn   = wid & 1;             // 0..1 (N strips of 32)
    const int lrow = lane & 15;
    const int lhi  = (lane >> 4) & 1;

    const int mtile = blockIdx.x >> 2;    // 64
    const int ntile = blockIdx.x & 3;     // 4
    const int m0 = mtile * T2_M;
    const int n0 = ntile * T2_N;
    const int kchunks = N_ROWS / CK;      // 256

    const int ra = tid >> 3;              // 0..31  (A row mod 32)
    const int sa = tid & 7;               // 0..7   (A 16B segment)
    const int rb = tid >> 2;              // 0..63  (B row)
    const int sb = tid & 3;               // 0..3   (B 16B segment)
    const float*  gA = A  + (size_t)(m0 + ra) * N_ROWS + sa * 4;
    const __half* gB = Yt + (size_t)(n0 + rb) * N_ROWS + sb * 8;

    float acc[2][4][4];
    #pragma unroll
    for (int mi = 0; mi < 2; mi++)
        #pragma unroll
        for (int ni = 0; ni < 4; ni++)
            #pragma unroll
            for (int i = 0; i < 4; i++) acc[mi][ni][i] = 0.f;
    float rsum[4] = {0.f, 0.f, 0.f, 0.f};

    auto issueB = [&](int kc) {
        if (kc < kchunks) {
            cpa16(sbase + B_OFF + (kc & 7) * B_ST + rb * (PAH * 2) + sb * 16,
                  gB + (size_t)kc * CK);
            cpa16(sbase + B_OFF + ((kc + 1) & 7) * B_ST + rb * (PAH * 2) + sb * 16,
                  gB + (size_t)(kc + 1) * CK);
        }
        asm volatile("cp.async.commit_group;" ::: "memory");
    };
    auto ldA = [&](int kc, float4* v) {
        #pragma unroll
        for (int i = 0; i < 4; i++)
            v[i] = *(const float4*)(gA + (size_t)i * 32 * N_ROWS + (size_t)kc * CK);
    };
    auto stA = [&](int kc, const float4* v) {
        const uint32_t aw = sbase + (kc & 3) * A_ST + ra * (PAH * 2) + sa * 8;
        #pragma unroll
        for (int i = 0; i < 4; i++) {
            uint32_t h01 = pack_h2(v[i].x, v[i].y);
            uint32_t h23 = pack_h2(v[i].z, v[i].w);
            asm volatile("st.shared.v2.b32 [%0], {%1,%2};"
                         :: "r"(aw + i * 32 * (PAH * 2)), "r"(h01), "r"(h23));
            rsum[i] += (v[i].x + v[i].y) + (v[i].z + v[i].w);
        }
    };
    auto mmaChunk = [&](int kc) {
        const uint32_t aBase = sbase + (kc & 3) * A_ST;
        const uint32_t bBase = sbase + B_OFF + (kc & 7) * B_ST;
        #pragma unroll
        for (int ks = 0; ks < 2; ks++) {
            uint32_t af[2][4], bf[4][2];
            #pragma unroll
            for (int mi = 0; mi < 2; mi++) {
                uint32_t ad = aBase + ((wm * 32 + mi * 16 + lrow) * PAH + ks * 16 + lhi * 8) * 2;
                ldsm4(af[mi][0], af[mi][1], af[mi][2], af[mi][3], ad);
            }
            #pragma unroll
            for (int np = 0; np < 2; np++) {
                uint32_t bd = bBase + ((wn * 32 + np * 16 + lrow) * PAH + ks * 16 + lhi * 8) * 2;
                uint32_t r0, r1, r2, r3;
                ldsm4(r0, r1, r2, r3, bd);
                bf[np * 2 + 0][0] = r0; bf[np * 2 + 0][1] = r2;
                bf[np * 2 + 1][0] = r1; bf[np * 2 + 1][1] = r3;
            }
            #pragma unroll
            for (int mi = 0; mi < 2; mi++)
                #pragma unroll
                for (int ni = 0; ni < 4; ni++)
                    mma_f16_k16(acc[mi][ni], af[mi], bf[ni]);
        }
    };

    // prologue
    float4 vA0[4], vA1[4];
    ldA(0, vA0);
    ldA(1, vA1);
    issueB(0);
    issueB(2);

    for (int kc = 0; kc < kchunks; kc += 2) {
        asm volatile("cp.async.wait_group %0;" :: "n"(1) : "memory");

        stA(kc, vA0);
        stA(kc + 1, vA1);
        int kn0 = kc + 2, kn1 = kc + 3;
        if (kn1 >= kchunks) { kn0 = kchunks - 2; kn1 = kchunks - 1; }
        ldA(kn0, vA0);
        ldA(kn1, vA1);

        __syncthreads();

        issueB(kc + 4);

        mmaChunk(kc);
        mmaChunk(kc + 1);
    }

    // rowsum reduce (8 lanes per row group)
    #pragma unroll
    for (int i = 0; i < 4; i++) {
        rsum[i] += __shfl_down_sync(0xffffffffu, rsum[i], 4, 8);
        rsum[i] += __shfl_down_sync(0xffffffffu, rsum[i], 2, 8);
        rsum[i] += __shfl_down_sync(0xffffffffu, rsum[i], 1, 8);
    }
    float* rs = (float*)(smem + RS_OFF);
    if (sa == 0) {
        #pragma unroll
        for (int i = 0; i < 4; i++)
            rs[i * 32 + ra] = 1.f / fmaxf(rsum[i], 1e-12f);
    }
    __syncthreads();

    // epilogue
    #pragma unroll
    for (int mi = 0; mi < 2; mi++) {
        const int r0 = wm * 32 + mi * 16 + gid;
        const float i0 = rs[r0];
        const float i1 = rs[r0 + 8];
        #pragma unroll
        for (int ni = 0; ni < 4; ni++) {
            const int cg = n0 + wn * 32 + ni * 8 + tig * 2;
            float2 bv = *(const float2*)(bias + cg);
            float2 v0, v1;
            v0.x = acc[mi][ni][0] * i0 + bv.x;
            v0.y = acc[mi][ni][1] * i0 + bv.y;
            v1.x = acc[mi][ni][2] * i1 + bv.x;
            v1.y = acc[mi][ni][3] * i1 + bv.y;
            *(float2*)(out + (size_t)(m0 + r0) * F_OUT + cg) = v0;
            *(float2*)(out + (size_t)(m0 + r0 + 8) * F_OUT + cg) = v1;
        }
    }
}

// ---------------- host ----------------
extern "C" void kernel_launch(void* const* d_in, const int* in_sizes, int n_in,
                              void* d_out, int out_size) {
    const float *A = nullptr, *X = nullptr, *W = nullptr, *Bi = nullptr;
    for (int i = 0; i < n_in; i++) {
        long s = in_sizes[i];
        if (s == (long)N_ROWS * N_ROWS)      A  = (const float*)d_in[i];
        else if (s == (long)N_ROWS * F_IN)   X  = (const float*)d_in[i];
        else if (s == (long)F_IN * F_OUT)    W  = (const float*)d_in[i];
        else if (s == (long)F_OUT)           Bi = (const float*)d_in[i];
    }

    void *xh = nullptr, *wth = nullptr, *yt = nullptr;
    cudaGetSymbolAddress(&xh, g_Xh);
    cudaGetSymbolAddress(&wth, g_Wth);
    cudaGetSymbolAddress(&yt, g_Yt);

    cudaFuncSetAttribute(gemm1_f16, cudaFuncAttributeMaxDynamicSharedMemorySize, G1_SMEM);
    cudaFuncSetAttribute(gemm2_f16, cudaFuncAttributeMaxDynamicSharedMemorySize, T2_SMEM);

    // merged prep: Xh conversion + W transpose in one launch
    prep_all<<<XH_BLOCKS + 128, 256>>>(X, (__half*)xh, W, (__half*)wth);

    // GEMM1: Yt[256,8192] = Wth @ Xh^T   (4 x 64 = 256 CTAs, tile 64x128)
    gemm1_f16<<<4 * 64, 256, G1_SMEM>>>((const __half*)wth, (const __half*)xh, (__half*)yt);

    // GEMM2: out[8192,256] = (A @ Yt^T)*inv_rowsum + bias  (64 x 4 = 256 CTAs)
    gemm2_f16<<<64 * 4, 256, T2_SMEM>>>(A, (const __half*)yt, (float*)d_out, Bi);
}